// round 15
// baseline (speedup 1.0000x reference)
#include <cuda_runtime.h>

#define N_NODES 100000
#define N_EDGES 1600000
#define F 48
#define FG (F / 4)            // 12 float4 groups per feature row
#define CAP 64                // bucket capacity per node (deg ~ Poisson(16))

// Scratch (static device arrays; no allocation allowed).
// g_cursor starts zeroed (static init) and is re-zeroed by gather_kernel at
// the end of every run -> no separate zero pass needed.
__device__ int   g_cursor[N_NODES];
__device__ int   g_col[N_NODES * CAP];           // bucketed CSR columns
// ys2: per node a 256B slot = two 128B-aligned half-rows of 96B each holding
// dinv[c] * (x[c] @ W^T):
//   bytes [0,96)    = groups 0..5
//   bytes [128,224) = groups 6..11
// slot N_NODES is never written -> stays zero (dummy target for tail edges).
__device__ float g_ys2[(N_NODES + 1) * 64];

// ---------------------------------------------------------------------------
// 1) bucket fill, 4 edges per thread via int4 loads
// ---------------------------------------------------------------------------
__global__ void fill_kernel(const int* __restrict__ ei) {
    int t = blockIdx.x * blockDim.x + threadIdx.x;
    if (t < N_EDGES / 4) {
        int4 r4 = __ldg(reinterpret_cast<const int4*>(ei) + t);
        int4 c4 = __ldg(reinterpret_cast<const int4*>(ei + N_EDGES) + t);
        int s0 = atomicAdd(&g_cursor[r4.x], 1);
        int s1 = atomicAdd(&g_cursor[r4.y], 1);
        int s2 = atomicAdd(&g_cursor[r4.z], 1);
        int s3 = atomicAdd(&g_cursor[r4.w], 1);
        if (s0 < CAP) g_col[r4.x * CAP + s0] = c4.x;
        if (s1 < CAP) g_col[r4.y * CAP + s1] = c4.y;
        if (s2 < CAP) g_col[r4.z * CAP + s2] = c4.z;
        if (s3 < CAP) g_col[r4.w * CAP + s3] = c4.w;
    }
}

// ---------------------------------------------------------------------------
// 2) transform: ys[n] = dinv[n] * (x[n] @ W^T), written in slot layout.
//    (Linear commutes with the per-node aggregation, so the GEMM runs FIRST,
//    merging the old scale and linear passes.  Bias+relu move to the gather.)
//    Block = 384 threads, 64 nodes; GEMM 8 outputs/thread from smem;
//    results staged in smem then stored as dinv-scaled float4 slots.
// ---------------------------------------------------------------------------
#define TNPB 64
__global__ __launch_bounds__(384)
void transform_kernel(const float* __restrict__ x,
                      const float* __restrict__ W) {
    __shared__ float Wt[F * F];                  // Wt[k*F + of] = W[of*F + k]
    __shared__ float xs[TNPB * F];
    __shared__ float os[TNPB * F];

    int tid = threadIdx.x;
    for (int i = tid; i < F * F; i += 384) {
        int of = i / F, k = i % F;
        Wt[k * F + of] = __ldg(&W[i]);
    }

    int node0 = blockIdx.x * TNPB;
    {   // stage x tile as float4 (2 per thread)
        const float4* src = reinterpret_cast<const float4*>(x);
        float4* dst = reinterpret_cast<float4*>(xs);
        int base = node0 * FG;
        #pragma unroll
        for (int r = 0; r < 2; r++) {
            int i = tid + r * 384;
            int gi = base + i;
            dst[i] = (gi < N_NODES * FG) ? __ldg(&src[gi])
                                         : make_float4(0.f, 0.f, 0.f, 0.f);
        }
    }
    __syncthreads();

    {   // GEMM: 8 nodes x 1 feature per thread
        int of  = tid % F;             // 0..47
        int nlb = tid / F;             // 0..7
        const float4* xs4 = reinterpret_cast<const float4*>(xs);
        float a0 = 0.f, a1 = 0.f, a2 = 0.f, a3 = 0.f;
        float a4 = 0.f, a5 = 0.f, a6 = 0.f, a7 = 0.f;
        #pragma unroll
        for (int k4 = 0; k4 < FG; k4++) {
            int kb = k4 * 4;
            float w0 = Wt[(kb + 0) * F + of];
            float w1 = Wt[(kb + 1) * F + of];
            float w2 = Wt[(kb + 2) * F + of];
            float w3 = Wt[(kb + 3) * F + of];
            #define DO_NODE(m, am)                                           \
            {                                                                \
                float4 av = xs4[(nlb + 8 * m) * FG + k4];                    \
                am = fmaf(av.x, w0, am); am = fmaf(av.y, w1, am);            \
                am = fmaf(av.z, w2, am); am = fmaf(av.w, w3, am);            \
            }
            DO_NODE(0, a0) DO_NODE(1, a1) DO_NODE(2, a2) DO_NODE(3, a3)
            DO_NODE(4, a4) DO_NODE(5, a5) DO_NODE(6, a6) DO_NODE(7, a7)
            #undef DO_NODE
        }
        os[(nlb +  0) * F + of] = a0;
        os[(nlb +  8) * F + of] = a1;
        os[(nlb + 16) * F + of] = a2;
        os[(nlb + 24) * F + of] = a3;
        os[(nlb + 32) * F + of] = a4;
        os[(nlb + 40) * F + of] = a5;
        os[(nlb + 48) * F + of] = a6;
        os[(nlb + 56) * F + of] = a7;
    }
    __syncthreads();

    {   // dinv-scaled slot stores (2 float4 per thread)
        #pragma unroll
        for (int r = 0; r < 2; r++) {
            int i = tid + r * 384;     // 0..767
            int nl = i / FG;
            int g  = i % FG;
            int n = node0 + nl;
            if (n < N_NODES) {
                int d = __ldg(&g_cursor[n]);
                float di = (d > 0) ? rsqrtf((float)d) : 0.0f;
                float4 v = *reinterpret_cast<const float4*>(&os[nl * F + g * 4]);
                v.x *= di; v.y *= di; v.z *= di; v.w *= di;
                int slot4 = (g < 6) ? g : (8 + (g - 6));
                reinterpret_cast<float4*>(g_ys2)[n * 16 + slot4] = v;
            }
        }
    }
}

// ---------------------------------------------------------------------------
// 3) gather + bias + relu (FINAL output) + cursor self-clean.
//    One warp per node (zero divergence, warps retire independently).
//    lane = oct*8+sub; oct = (edge-of-pair e, plane p); 8 edges/iter.
//    Main loop select-free (full octets); single masked tail iteration.
// ---------------------------------------------------------------------------
__global__ __launch_bounds__(512)
void gather_kernel(const float* __restrict__ b,
                   float* __restrict__ out) {
    int n = (blockIdx.x * 512 + threadIdx.x) >> 5;   // warp id == node
    if (n >= N_NODES) return;
    int lane = threadIdx.x & 31;
    int oct = lane >> 3;
    int sub = lane & 7;
    int e = oct >> 1;                  // which edge of the pair
    int p = oct & 1;                   // which 96B half-row
    unsigned sof = (unsigned)(p * 128) + (sub < 6 ? (unsigned)(sub * 16) : 0u);

    int degc = g_cursor[n];
    int deg = min(degc, CAP);
    if (lane == 0) g_cursor[n] = 0;    // self-clean for the next replay
    const int* bucket = &g_col[n * CAP];
    const char* yb = reinterpret_cast<const char*>(g_ys2);

    float4 acc = make_float4(0.f, 0.f, 0.f, 0.f);
    int nfull = deg & ~7;
    int j0 = 0;
    for (; j0 < nfull; j0 += 8) {      // select-free main loop
        int c0 = __ldg(&bucket[j0 + 0 + e]);
        int c1 = __ldg(&bucket[j0 + 2 + e]);
        int c2 = __ldg(&bucket[j0 + 4 + e]);
        int c3 = __ldg(&bucket[j0 + 6 + e]);
        float4 v0 = __ldg(reinterpret_cast<const float4*>(yb + (unsigned)c0 * 256u + sof));
        float4 v1 = __ldg(reinterpret_cast<const float4*>(yb + (unsigned)c1 * 256u + sof));
        float4 v2 = __ldg(reinterpret_cast<const float4*>(yb + (unsigned)c2 * 256u + sof));
        float4 v3 = __ldg(reinterpret_cast<const float4*>(yb + (unsigned)c3 * 256u + sof));
        acc.x += (v0.x + v1.x) + (v2.x + v3.x);
        acc.y += (v0.y + v1.y) + (v2.y + v3.y);
        acc.z += (v0.z + v1.z) + (v2.z + v3.z);
        acc.w += (v0.w + v1.w) + (v2.w + v3.w);
    }
    if (j0 < deg) {                    // one masked tail iteration
        int i0 = j0 + 0 + e, i1 = j0 + 2 + e, i2 = j0 + 4 + e, i3 = j0 + 6 + e;
        int c0 = (i0 < deg) ? __ldg(&bucket[i0]) : N_NODES;
        int c1 = (i1 < deg) ? __ldg(&bucket[i1]) : N_NODES;
        int c2 = (i2 < deg) ? __ldg(&bucket[i2]) : N_NODES;
        int c3 = (i3 < deg) ? __ldg(&bucket[i3]) : N_NODES;
        float4 v0 = __ldg(reinterpret_cast<const float4*>(yb + (unsigned)c0 * 256u + sof));
        float4 v1 = __ldg(reinterpret_cast<const float4*>(yb + (unsigned)c1 * 256u + sof));
        float4 v2 = __ldg(reinterpret_cast<const float4*>(yb + (unsigned)c2 * 256u + sof));
        float4 v3 = __ldg(reinterpret_cast<const float4*>(yb + (unsigned)c3 * 256u + sof));
        acc.x += (v0.x + v1.x) + (v2.x + v3.x);
        acc.y += (v0.y + v1.y) + (v2.y + v3.y);
        acc.z += (v0.z + v1.z) + (v2.z + v3.z);
        acc.w += (v0.w + v1.w) + (v2.w + v3.w);
    }

    // combine the two edge-of-pair octets (lane ^ 16)
    acc.x += __shfl_xor_sync(0xffffffffu, acc.x, 16);
    acc.y += __shfl_xor_sync(0xffffffffu, acc.y, 16);
    acc.z += __shfl_xor_sync(0xffffffffu, acc.z, 16);
    acc.w += __shfl_xor_sync(0xffffffffu, acc.w, 16);

    if (lane < 16 && sub < 6) {
        float di = (deg > 0) ? rsqrtf((float)deg) : 0.0f;
        int g = p * 6 + sub;
        float4 bb = __ldg(reinterpret_cast<const float4*>(&b[g * 4]));
        float4 r;
        r.x = fmaxf(fmaf(acc.x, di, bb.x), 0.f);
        r.y = fmaxf(fmaf(acc.y, di, bb.y), 0.f);
        r.z = fmaxf(fmaf(acc.z, di, bb.z), 0.f);
        r.w = fmaxf(fmaf(acc.w, di, bb.w), 0.f);
        *reinterpret_cast<float4*>(&out[(size_t)n * F + g * 4]) = r;
    }
}

// ---------------------------------------------------------------------------
extern "C" void kernel_launch(void* const* d_in, const int* in_sizes, int n_in,
                              void* d_out, int out_size) {
    const float* x  = (const float*)d_in[0];   // [N_NODES, F]
    const int*   ei = (const int*)d_in[1];     // [2, N_EDGES]
    const float* W  = (const float*)d_in[2];   // [F, F]
    const float* b  = (const float*)d_in[3];   // [F]
    float* out = (float*)d_out;

    fill_kernel<<<(N_EDGES / 4 + 255) / 256, 256>>>(ei);
    transform_kernel<<<(N_NODES + TNPB - 1) / TNPB, 384>>>(x, W);
    gather_kernel<<<(N_NODES * 32 + 511) / 512, 512>>>(b, out);
}

// round 16
// speedup vs baseline: 3.7633x; 3.7633x over previous
#include <cuda_runtime.h>

#define N_NODES 100000
#define N_EDGES 1600000
#define F 48
#define FG (F / 4)            // 12 float4 groups per feature row
#define CAP 64                // bucket capacity per node (deg ~ Poisson(16))
#define NPB 64                // nodes per block in fused gather+linear
#define BLK 384               // 64 nodes x 6 threads

// Scratch (static device arrays; no allocation allowed)
__device__ int   g_cursor[N_NODES];            // doubles as degree after fill
__device__ float g_dinv[N_NODES];
__device__ int   g_col[N_NODES * CAP];         // bucketed CSR columns
__device__ float g_xs[N_NODES * F];            // xs[c] = dinv[c] * x[c]

// ---------------------------------------------------------------------------
// 1) zero cursors (vectorized)
// ---------------------------------------------------------------------------
__global__ void zero_kernel() {
    int i = blockIdx.x * blockDim.x + threadIdx.x;
    int4* c4 = reinterpret_cast<int4*>(g_cursor);
    if (i < N_NODES / 4) c4[i] = make_int4(0, 0, 0, 0);
}

// ---------------------------------------------------------------------------
// 2) bucket fill: ONE edge per thread (1.6M independent atomic chains in
//    flight -> atomic-return latency hidden by thread count, not ILP)
// ---------------------------------------------------------------------------
__global__ void fill_kernel(const int* __restrict__ ei) {
    int e = blockIdx.x * blockDim.x + threadIdx.x;
    if (e < N_EDGES) {
        int r = __ldg(&ei[e]);
        int c = __ldg(&ei[N_EDGES + e]);
        int s = atomicAdd(&g_cursor[r], 1);
        if (s < CAP) g_col[r * CAP + s] = c;
    }
}

// ---------------------------------------------------------------------------
// 3) dinv + pre-scaled features:  xs[n] = dinv[n] * x[n]
// ---------------------------------------------------------------------------
__global__ void scale_kernel(const float* __restrict__ x) {
    int t = blockIdx.x * blockDim.x + threadIdx.x;
    if (t < N_NODES * FG) {
        int n = t / FG;
        int d = __ldg(&g_cursor[n]);
        float di = (d > 0) ? rsqrtf((float)d) : 0.0f;
        if (t % FG == 0) g_dinv[n] = di;
        float4 v = __ldg(reinterpret_cast<const float4*>(x) + t);
        v.x *= di; v.y *= di; v.z *= di; v.w *= di;
        reinterpret_cast<float4*>(g_xs)[t] = v;
    }
}

// ---------------------------------------------------------------------------
// 4) fused gather-aggregate + linear + relu.  (R8 kernel, measured 63.0us)
//    Block = 384 threads, 64 nodes; 6 threads/node, each owning TWO float4
//    groups (g and g+6) of the feature row -> 8 independent 16B loads per
//    4-edge iteration.
// ---------------------------------------------------------------------------
__global__ __launch_bounds__(BLK, 2)
void gather_linear_kernel(const float* __restrict__ W,
                          const float* __restrict__ b,
                          float* __restrict__ out) {
    __shared__ float Wt[F * F];                 // Wt[k*F + of] = W[of*F + k]
    __shared__ float agg_s[NPB * F];

    int tid = threadIdx.x;
    for (int i = tid; i < F * F; i += BLK) {
        int of = i / F, k = i % F;
        Wt[k * F + of] = W[i];
    }

    int node0 = blockIdx.x * NPB;

    // ---- gather phase ----
    {
        int nl = tid / 6;           // 0..63
        int h  = tid % 6;           // 0..5  -> groups h and h+6
        int n = node0 + nl;
        float4 acc0 = make_float4(0.f, 0.f, 0.f, 0.f);
        float4 acc1 = make_float4(0.f, 0.f, 0.f, 0.f);
        if (n < N_NODES) {
            int deg = min(__ldg(&g_cursor[n]), CAP);
            const int4* bucket4 = reinterpret_cast<const int4*>(&g_col[n * CAP]);
            const int*  bucket  = &g_col[n * CAP];
            const char* xb = reinterpret_cast<const char*>(g_xs);
            unsigned o0 = (unsigned)(h * 16);        // group h
            unsigned o1 = o0 + 96u;                  // group h+6

            int nquads = deg >> 2;
            for (int q = 0; q < nquads; q++) {
                int4 cc = __ldg(&bucket4[q]);
                unsigned b0 = (unsigned)cc.x * 192u;
                unsigned b1 = (unsigned)cc.y * 192u;
                unsigned b2 = (unsigned)cc.z * 192u;
                unsigned b3 = (unsigned)cc.w * 192u;
                float4 u0 = __ldg(reinterpret_cast<const float4*>(xb + b0 + o0));
                float4 u1 = __ldg(reinterpret_cast<const float4*>(xb + b1 + o0));
                float4 u2 = __ldg(reinterpret_cast<const float4*>(xb + b2 + o0));
                float4 u3 = __ldg(reinterpret_cast<const float4*>(xb + b3 + o0));
                float4 w0 = __ldg(reinterpret_cast<const float4*>(xb + b0 + o1));
                float4 w1 = __ldg(reinterpret_cast<const float4*>(xb + b1 + o1));
                float4 w2 = __ldg(reinterpret_cast<const float4*>(xb + b2 + o1));
                float4 w3 = __ldg(reinterpret_cast<const float4*>(xb + b3 + o1));
                acc0.x += u0.x + u1.x + u2.x + u3.x;
                acc0.y += u0.y + u1.y + u2.y + u3.y;
                acc0.z += u0.z + u1.z + u2.z + u3.z;
                acc0.w += u0.w + u1.w + u2.w + u3.w;
                acc1.x += w0.x + w1.x + w2.x + w3.x;
                acc1.y += w0.y + w1.y + w2.y + w3.y;
                acc1.z += w0.z + w1.z + w2.z + w3.z;
                acc1.w += w0.w + w1.w + w2.w + w3.w;
            }
            for (int j = nquads << 2; j < deg; j++) {
                unsigned bb = (unsigned)__ldg(&bucket[j]) * 192u;
                float4 u = __ldg(reinterpret_cast<const float4*>(xb + bb + o0));
                float4 w = __ldg(reinterpret_cast<const float4*>(xb + bb + o1));
                acc0.x += u.x; acc0.y += u.y; acc0.z += u.z; acc0.w += u.w;
                acc1.x += w.x; acc1.y += w.y; acc1.z += w.z; acc1.w += w.w;
            }
            float di = __ldg(&g_dinv[n]);
            acc0.x *= di; acc0.y *= di; acc0.z *= di; acc0.w *= di;
            acc1.x *= di; acc1.y *= di; acc1.z *= di; acc1.w *= di;
        }
        float* d0 = &agg_s[nl * F + h * 4];
        d0[0] = acc0.x; d0[1] = acc0.y; d0[2] = acc0.z; d0[3] = acc0.w;
        float* d1 = d0 + 24;        // group h+6
        d1[0] = acc1.x; d1[1] = acc1.y; d1[2] = acc1.z; d1[3] = acc1.w;
    }
    __syncthreads();

    // ---- linear + bias + relu (8 outputs per thread) ----
    {
        int of  = tid % F;          // 0..47
        int nlb = tid / F;          // 0..7
        float bias = __ldg(&b[of]);
        float a0 = bias, a1 = bias, a2 = bias, a3 = bias;
        float a4 = bias, a5 = bias, a6 = bias, a7 = bias;
        #pragma unroll
        for (int k = 0; k < F; k++) {
            float wv = Wt[k * F + of];
            a0 = fmaf(agg_s[(nlb +  0) * F + k], wv, a0);
            a1 = fmaf(agg_s[(nlb +  8) * F + k], wv, a1);
            a2 = fmaf(agg_s[(nlb + 16) * F + k], wv, a2);
            a3 = fmaf(agg_s[(nlb + 24) * F + k], wv, a3);
            a4 = fmaf(agg_s[(nlb + 32) * F + k], wv, a4);
            a5 = fmaf(agg_s[(nlb + 40) * F + k], wv, a5);
            a6 = fmaf(agg_s[(nlb + 48) * F + k], wv, a6);
            a7 = fmaf(agg_s[(nlb + 56) * F + k], wv, a7);
        }
        int n0 = node0 + nlb;
        if (n0 +  0 < N_NODES) out[(size_t)(n0 +  0) * F + of] = fmaxf(a0, 0.f);
        if (n0 +  8 < N_NODES) out[(size_t)(n0 +  8) * F + of] = fmaxf(a1, 0.f);
        if (n0 + 16 < N_NODES) out[(size_t)(n0 + 16) * F + of] = fmaxf(a2, 0.f);
        if (n0 + 24 < N_NODES) out[(size_t)(n0 + 24) * F + of] = fmaxf(a3, 0.f);
        if (n0 + 32 < N_NODES) out[(size_t)(n0 + 32) * F + of] = fmaxf(a4, 0.f);
        if (n0 + 40 < N_NODES) out[(size_t)(n0 + 40) * F + of] = fmaxf(a5, 0.f);
        if (n0 + 48 < N_NODES) out[(size_t)(n0 + 48) * F + of] = fmaxf(a6, 0.f);
        if (n0 + 56 < N_NODES) out[(size_t)(n0 + 56) * F + of] = fmaxf(a7, 0.f);
    }
}

// ---------------------------------------------------------------------------
extern "C" void kernel_launch(void* const* d_in, const int* in_sizes, int n_in,
                              void* d_out, int out_size) {
    const float* x  = (const float*)d_in[0];   // [N_NODES, F]
    const int*   ei = (const int*)d_in[1];     // [2, N_EDGES]
    const float* W  = (const float*)d_in[2];   // [F, F]
    const float* b  = (const float*)d_in[3];   // [F]
    float* out = (float*)d_out;

    zero_kernel<<<(N_NODES / 4 + 255) / 256, 256>>>();
    fill_kernel<<<(N_EDGES + 255) / 256, 256>>>(ei);
    scale_kernel<<<(N_NODES * FG + 255) / 256, 256>>>(x);
    gather_linear_kernel<<<(N_NODES + NPB - 1) / NPB, BLK>>>(W, b, out);
}